// round 1
// baseline (speedup 1.0000x reference)
#include <cuda_runtime.h>

#define NUM_NODES 500000
#define D 128
#define U 32
#define T 4
#define A 32
#define N_SRC 65536
#define B 8192
#define E 262144
#define BB 32  // batch rows per finalize block

// Scratch accumulator: agg[b][t][u]  (B*T*U floats = 4 MB)
__device__ float g_agg[B * T * U];

// ---------------------------------------------------------------------------
// Kernel 1: zero the accumulator (float4 stores)
// ---------------------------------------------------------------------------
__global__ void zero_agg_kernel() {
    int i = blockIdx.x * blockDim.x + threadIdx.x;
    ((float4*)g_agg)[i] = make_float4(0.f, 0.f, 0.f, 0.f);
}

// ---------------------------------------------------------------------------
// Kernel 2: edge aggregation with vectorized global reductions.
// 8 threads per edge; each thread moves one float4 (16 B) of the U=32 row.
//   msgs[t,e] = node_type_embeddings[input_nodes[edge_src[t,e]], t, :]
//   agg[edge_dst[t,e], t, :] += msgs
// ---------------------------------------------------------------------------
__global__ void edge_agg_kernel(const float* __restrict__ nte_tab,
                                const int* __restrict__ input_nodes,
                                const int* __restrict__ edge_src,
                                const int* __restrict__ edge_dst) {
    const int t   = blockIdx.y;
    const int e   = blockIdx.x * 32 + (threadIdx.x >> 3);   // 32 edges / block
    const int sub = threadIdx.x & 7;                        // float4 slot in row

    const int src  = __ldg(&edge_src[t * E + e]);
    const int dst  = __ldg(&edge_dst[t * E + e]);
    const int node = __ldg(&input_nodes[src]);

    const float4* row = (const float4*)nte_tab + (size_t)(node * T + t) * (U / 4) + sub;
    float4 v = __ldg(row);

    float* p = g_agg + ((size_t)dst * T + t) * U + sub * 4;
    asm volatile("red.global.add.v4.f32 [%0], {%1,%2,%3,%4};"
                 :: "l"(p), "f"(v.x), "f"(v.y), "f"(v.z), "f"(v.w)
                 : "memory");
}

// ---------------------------------------------------------------------------
// Kernel 3: attention + combine + trans GEMM + residual + L2-normalize.
// One block handles BB=32 batch rows with 256 threads (8 warps).
// trans_w stays in L1/L2 (64 KB, shared across all warps of all blocks).
// ---------------------------------------------------------------------------
__global__ __launch_bounds__(256) void finalize_kernel(
    const float* __restrict__ node_emb,     // [NUM_NODES][D]
    const float* __restrict__ w,            // [T][U][D]
    const float* __restrict__ ws1,          // [T][U][A]
    const float* __restrict__ ws2,          // [T][A]
    const int*  __restrict__ out_nodes,     // [B]
    float*      __restrict__ out)           // [B][T][D]
{
    __shared__ float nte_s[BB][T * U];      // 16 KB
    __shared__ float scores_s[BB][T];
    __shared__ float att_s[BB][T];
    __shared__ float comb_s[BB][U];         // 4 KB

    const int b0   = blockIdx.x * BB;
    const int tid  = threadIdx.x;
    const int lane = tid & 31;
    const int warp = tid >> 5;              // 8 warps

    // Load nte for BB rows (contiguous 16 KB, float4)
    {
        const float4* s4 = (const float4*)(g_agg + (size_t)b0 * T * U);
        float4* d4 = (float4*)&nte_s[0][0];
        #pragma unroll
        for (int i = tid; i < BB * T * U / 4; i += 256) d4[i] = s4[i];
    }
    __syncthreads();

    // Stage A: h = tanh(nte @ ws1[t]); score = h . ws2[t]
    // warp-task = (bb, t); lane = a
    for (int task = warp; task < BB * T; task += 8) {
        const int bb = task >> 2, t = task & 3;
        float acc = 0.f;
        #pragma unroll
        for (int u = 0; u < U; u++)
            acc += nte_s[bb][t * U + u] * __ldg(&ws1[(t * U + u) * A + lane]);
        float sc = tanhf(acc) * __ldg(&ws2[t * A + lane]);
        #pragma unroll
        for (int o = 16; o; o >>= 1) sc += __shfl_xor_sync(0xFFFFFFFFu, sc, o);
        if (lane == 0) scores_s[bb][t] = sc;
    }
    __syncthreads();

    // Softmax over T=4 (one thread per batch row)
    if (tid < BB) {
        float s0 = scores_s[tid][0], s1 = scores_s[tid][1];
        float s2 = scores_s[tid][2], s3 = scores_s[tid][3];
        float m = fmaxf(fmaxf(s0, s1), fmaxf(s2, s3));
        float e0 = __expf(s0 - m), e1 = __expf(s1 - m);
        float e2 = __expf(s2 - m), e3 = __expf(s3 - m);
        float inv = 1.f / (e0 + e1 + e2 + e3);
        att_s[tid][0] = e0 * inv; att_s[tid][1] = e1 * inv;
        att_s[tid][2] = e2 * inv; att_s[tid][3] = e3 * inv;
    }
    __syncthreads();

    // combined[bb][u] = sum_t att[bb][t] * nte[bb][t][u]
    #pragma unroll
    for (int i = tid; i < BB * U; i += 256) {
        const int bb = i >> 5, u = i & 31;
        float c = 0.f;
        #pragma unroll
        for (int t = 0; t < T; t++) c += att_s[bb][t] * nte_s[bb][t * U + u];
        comb_s[bb][u] = c;
    }
    __syncthreads();

    // Stage B: out[b,t,:] = normalize(node_emb[out_nodes[b],:] + combined[b] @ w[t])
    // warp-task = (bb, t); lane = d/4 (float4 over D=128)
    for (int task = warp; task < BB * T; task += 8) {
        const int bb = task >> 2, t = task & 3;
        const int b  = b0 + bb;

        float4 o = make_float4(0.f, 0.f, 0.f, 0.f);
        const float4* w4 = (const float4*)w + (size_t)t * U * (D / 4) + lane;
        #pragma unroll
        for (int u = 0; u < U; u++) {
            const float  c  = comb_s[bb][u];
            const float4 wv = __ldg(&w4[u * (D / 4)]);
            o.x += c * wv.x; o.y += c * wv.y; o.z += c * wv.z; o.w += c * wv.w;
        }

        const int nidx = __ldg(&out_nodes[b]);
        const float4 nv = __ldg((const float4*)node_emb + (size_t)nidx * (D / 4) + lane);
        o.x += nv.x; o.y += nv.y; o.z += nv.z; o.w += nv.w;

        float ss = o.x * o.x + o.y * o.y + o.z * o.z + o.w * o.w;
        #pragma unroll
        for (int off = 16; off; off >>= 1) ss += __shfl_xor_sync(0xFFFFFFFFu, ss, off);

        const float scale = 1.f / fmaxf(sqrtf(ss), 1e-12f);
        o.x *= scale; o.y *= scale; o.z *= scale; o.w *= scale;

        ((float4*)out)[(size_t)(b * T + t) * (D / 4) + lane] = o;
    }
}

// ---------------------------------------------------------------------------
// Launch
// ---------------------------------------------------------------------------
extern "C" void kernel_launch(void* const* d_in, const int* in_sizes, int n_in,
                              void* d_out, int out_size) {
    const float* node_emb     = (const float*)d_in[0];  // [500000][128]
    const float* nte_tab      = (const float*)d_in[1];  // [500000][4][32]
    const float* trans_w      = (const float*)d_in[2];  // [4][32][128]
    const float* trans_w_s1   = (const float*)d_in[3];  // [4][32][32]
    const float* trans_w_s2   = (const float*)d_in[4];  // [4][32][1]
    const int*   input_nodes  = (const int*)d_in[5];    // [65536]
    const int*   output_nodes = (const int*)d_in[6];    // [8192]
    const int*   edge_src     = (const int*)d_in[7];    // [4][262144]
    const int*   edge_dst     = (const int*)d_in[8];    // [4][262144]
    float*       out          = (float*)d_out;          // [8192][4][128]

    zero_agg_kernel<<<(B * T * U / 4) / 256, 256>>>();

    dim3 grid_e(E / 32, T);
    edge_agg_kernel<<<grid_e, 256>>>(nte_tab, input_nodes, edge_src, edge_dst);

    finalize_kernel<<<B / BB, 256>>>(node_emb, trans_w, trans_w_s1, trans_w_s2,
                                     output_nodes, out);
}

// round 3
// speedup vs baseline: 1.1723x; 1.1723x over previous
#include <cuda_runtime.h>

#define NUM_NODES 500000
#define D 128
#define U 32
#define T 4
#define A 32
#define N_SRC 65536
#define B 8192
#define E 262144
#define BB 32  // batch rows per finalize block

// Scratch accumulator: agg[b][t][u]  (B*T*U floats = 4 MB)
__device__ float g_agg[B * T * U];

// ---------------------------------------------------------------------------
// Kernel 0: zero the accumulator (float4 stores) — known graph-capture-safe.
// ---------------------------------------------------------------------------
__global__ void zero_agg_kernel() {
    int i = blockIdx.x * blockDim.x + threadIdx.x;
    ((float4*)g_agg)[i] = make_float4(0.f, 0.f, 0.f, 0.f);
}

// ---------------------------------------------------------------------------
// Kernel 1: edge aggregation with vectorized global reductions.
// 8 threads per edge; each thread moves one float4 (16 B) of the U=32 row.
//   agg[edge_dst[t,e], t, :] += node_type_embeddings[input_nodes[edge_src[t,e]], t, :]
// ---------------------------------------------------------------------------
__global__ void edge_agg_kernel(const float* __restrict__ nte_tab,
                                const int* __restrict__ input_nodes,
                                const int* __restrict__ edge_src,
                                const int* __restrict__ edge_dst) {
    const int t   = blockIdx.y;
    const int e   = blockIdx.x * 32 + (threadIdx.x >> 3);   // 32 edges / block
    const int sub = threadIdx.x & 7;                        // float4 slot in row

    const int src  = __ldg(&edge_src[t * E + e]);
    const int dst  = __ldg(&edge_dst[t * E + e]);
    const int node = __ldg(&input_nodes[src]);

    const float4* row = (const float4*)nte_tab + (size_t)(node * T + t) * (U / 4) + sub;
    float4 v = __ldg(row);

    float* p = g_agg + ((size_t)dst * T + t) * U + sub * 4;
    asm volatile("red.global.add.v4.f32 [%0], {%1,%2,%3,%4};"
                 :: "l"(p), "f"(v.x), "f"(v.y), "f"(v.z), "f"(v.w)
                 : "memory");
}

// ---------------------------------------------------------------------------
// Kernel 2: attention + combine + trans GEMM + residual + L2-normalize.
// One block = BB=32 batch rows, 256 threads (8 warps).
// Warp w owns t = w&3 and batch-half = w>>2; weights live in REGISTERS
// across the 16 batch rows (16x less L1 traffic than per-task reloads).
// ---------------------------------------------------------------------------
__global__ __launch_bounds__(256) void finalize_kernel(
    const float* __restrict__ node_emb,     // [NUM_NODES][D]
    const float* __restrict__ w,            // [T][U][D]
    const float* __restrict__ ws1,          // [T][U][A]
    const float* __restrict__ ws2,          // [T][A]
    const int*  __restrict__ out_nodes,     // [B]
    float*      __restrict__ out)           // [B][T][D]
{
    __shared__ float nte_s[BB][T * U];      // 16 KB
    __shared__ float scores_s[BB][T];
    __shared__ float att_s[BB][T];
    __shared__ float comb_s[BB][U];         // 4 KB

    const int b0   = blockIdx.x * BB;
    const int tid  = threadIdx.x;
    const int lane = tid & 31;
    const int warp = tid >> 5;              // 8 warps
    const int t    = warp & 3;              // attention head type
    const int half = warp >> 2;             // 0 or 1: which 16 batch rows
    const int bbase = half * 16;

    // Register-cache attention weights for this warp's t (lane = a index)
    float w1r[U];
    #pragma unroll
    for (int u = 0; u < U; u++) w1r[u] = __ldg(&ws1[(t * U + u) * A + lane]);
    const float w2r = __ldg(&ws2[t * A + lane]);

    // Load nte for BB rows (contiguous 16 KB, float4)
    {
        const float4* s4 = (const float4*)(g_agg + (size_t)b0 * T * U);
        float4* d4 = (float4*)&nte_s[0][0];
        #pragma unroll
        for (int i = tid; i < BB * T * U / 4; i += 256) d4[i] = s4[i];
    }
    __syncthreads();

    // Stage A: score[bb][t] = sum_a tanh(sum_u nte*ws1)[a] * ws2[a]
    #pragma unroll
    for (int i = 0; i < 16; i++) {
        const int bb = bbase + i;
        float acc = 0.f;
        #pragma unroll
        for (int u = 0; u < U; u++) acc += nte_s[bb][t * U + u] * w1r[u];
        float sc = tanhf(acc) * w2r;
        #pragma unroll
        for (int o = 16; o; o >>= 1) sc += __shfl_xor_sync(0xFFFFFFFFu, sc, o);
        if (lane == 0) scores_s[bb][t] = sc;
    }
    __syncthreads();

    // Softmax over T=4 (one thread per batch row)
    if (tid < BB) {
        float s0 = scores_s[tid][0], s1 = scores_s[tid][1];
        float s2 = scores_s[tid][2], s3 = scores_s[tid][3];
        float m = fmaxf(fmaxf(s0, s1), fmaxf(s2, s3));
        float e0 = __expf(s0 - m), e1 = __expf(s1 - m);
        float e2 = __expf(s2 - m), e3 = __expf(s3 - m);
        float inv = 1.f / (e0 + e1 + e2 + e3);
        att_s[tid][0] = e0 * inv; att_s[tid][1] = e1 * inv;
        att_s[tid][2] = e2 * inv; att_s[tid][3] = e3 * inv;
    }
    __syncthreads();

    // combined[bb][u] = sum_t att[bb][t] * nte[bb][t][u]
    #pragma unroll
    for (int i = tid; i < BB * U; i += 256) {
        const int bb = i >> 5, u = i & 31;
        float c = 0.f;
        #pragma unroll
        for (int tt = 0; tt < T; tt++) c += att_s[bb][tt] * nte_s[bb][tt * U + u];
        comb_s[bb][u] = c;
    }
    __syncthreads();

    // Stage B: out[b,t,:] = normalize(node_emb[out_nodes[b],:] + combined[b] @ w[t])
    // lane owns float4 slice of D; w chunked through registers, reused over 16 rows.
    float4 acc[16];
    #pragma unroll
    for (int i = 0; i < 16; i++) acc[i] = make_float4(0.f, 0.f, 0.f, 0.f);

    const float4* wbase = (const float4*)w + (size_t)t * U * (D / 4) + lane;
    #pragma unroll
    for (int uc = 0; uc < U; uc += 8) {
        float4 wr[8];
        #pragma unroll
        for (int j = 0; j < 8; j++) wr[j] = __ldg(&wbase[(uc + j) * (D / 4)]);
        #pragma unroll
        for (int i = 0; i < 16; i++) {
            const int bb = bbase + i;
            #pragma unroll
            for (int j = 0; j < 8; j++) {
                const float c = comb_s[bb][uc + j];
                acc[i].x += c * wr[j].x; acc[i].y += c * wr[j].y;
                acc[i].z += c * wr[j].z; acc[i].w += c * wr[j].w;
            }
        }
    }

    #pragma unroll
    for (int i = 0; i < 16; i++) {
        const int bb = bbase + i;
        const int b  = b0 + bb;

        const int nidx = __ldg(&out_nodes[b]);
        const float4 nv = __ldg((const float4*)node_emb + (size_t)nidx * (D / 4) + lane);
        float4 o = acc[i];
        o.x += nv.x; o.y += nv.y; o.z += nv.z; o.w += nv.w;

        float ss = o.x * o.x + o.y * o.y + o.z * o.z + o.w * o.w;
        #pragma unroll
        for (int off = 16; off; off >>= 1) ss += __shfl_xor_sync(0xFFFFFFFFu, ss, off);

        const float scale = 1.f / fmaxf(sqrtf(ss), 1e-12f);
        o.x *= scale; o.y *= scale; o.z *= scale; o.w *= scale;

        ((float4*)out)[(size_t)(b * T + t) * (D / 4) + lane] = o;
    }
}

// ---------------------------------------------------------------------------
// Launch
// ---------------------------------------------------------------------------
extern "C" void kernel_launch(void* const* d_in, const int* in_sizes, int n_in,
                              void* d_out, int out_size) {
    const float* node_emb     = (const float*)d_in[0];  // [500000][128]
    const float* nte_tab      = (const float*)d_in[1];  // [500000][4][32]
    const float* trans_w      = (const float*)d_in[2];  // [4][32][128]
    const float* trans_w_s1   = (const float*)d_in[3];  // [4][32][32]
    const float* trans_w_s2   = (const float*)d_in[4];  // [4][32][1]
    const int*   input_nodes  = (const int*)d_in[5];    // [65536]
    const int*   output_nodes = (const int*)d_in[6];    // [8192]
    const int*   edge_src     = (const int*)d_in[7];    // [4][262144]
    const int*   edge_dst     = (const int*)d_in[8];    // [4][262144]
    float*       out          = (float*)d_out;          // [8192][4][128]

    zero_agg_kernel<<<(B * T * U / 4) / 256, 256>>>();

    dim3 grid_e(E / 32, T);
    edge_agg_kernel<<<grid_e, 256>>>(nte_tab, input_nodes, edge_src, edge_dst);

    finalize_kernel<<<B / BB, 256>>>(node_emb, trans_w, trans_w_s1, trans_w_s2,
                                     output_nodes, out);
}